// round 14
// baseline (speedup 1.0000x reference)
#include <cuda_runtime.h>

// Problem constants (from reference)
#define VOCAB      30000
#define N_PRE      20000
#define VEC_DIM    300
#define INPUT_SIZE 10000   // VOCAB - N_PRE
#define HIDDEN     256
#define OUT_DIM    556     // VEC_DIM + HIDDEN
#define N_TOKENS   4096    // 8 * 512
#define VEC4       (VEC_DIM / 4)     // 75 float4 per vector row
#define VEC_ITEMS  (N_TOKENS * VEC4) // 307200 float4 copy items

#define GRID       1024
#define TPB        256
#define TOK_PER_BLK 4                // 1024 * 4 = 4096 tokens
#define THREADS_TOT (GRID * TPB)     // 262144; vector items: 1 or 2 per thread

// Near-single-wave fused kernel. Each thread:
//   - 4 hidden outputs (h = tid) for tokens tok0..tok0+3  (4 independent gathers)
//   - 1..2 vector float4 copy items (flat index)
// ALL loads are issued before any store (front-batched -> deep MLP), so the
// whole block's memory latency overlaps inside one block lifetime. Grid is
// sized for ~1 wave to avoid the (n_waves-1)*(T_CTA + T_wave_trans) tax that
// bound every previous variant at ~9us.
__global__ __launch_bounds__(TPB)
void encoder_fused(const int* __restrict__ batch,
                   const float* __restrict__ vectors,
                   const float* __restrict__ W,
                   const float* __restrict__ b,
                   float* __restrict__ out)
{
    const int bid = blockIdx.x;
    const int tid = threadIdx.x;

    // ---- stage hidden-part token indices through smem (1 LDG per block) ----
    __shared__ int s_idx[TOK_PER_BLK];
    const int tok0 = bid * TOK_PER_BLK;
    if (tid < TOK_PER_BLK)
        s_idx[tid] = batch[tok0 + tid];

    // ---- vector-part indices (independent loads, overlap the smem fill) ----
    const int k1  = bid * TPB + tid;             // always < VEC_ITEMS
    const int vt1 = k1 / VEC4;
    const int vq1 = k1 - vt1 * VEC4;
    const int t1  = batch[vt1];

    const int  k2   = k1 + THREADS_TOT;          // 262144..524287
    const bool has2 = (k2 < VEC_ITEMS);
    int vt2 = 0, vq2 = 0, t2 = N_PRE;            // default: write zeros path unused
    if (has2) {
        vt2 = k2 / VEC4;
        vq2 = k2 - vt2 * VEC4;
        t2  = batch[vt2];
    }

    const float bias = b[tid];                   // tiny, L2-resident
    __syncthreads();

    // ---- front-batch ALL data loads ----
    int ts[TOK_PER_BLK];
#pragma unroll
    for (int j = 0; j < TOK_PER_BLK; j++)
        ts[j] = s_idx[j];

    float w[TOK_PER_BLK];
#pragma unroll
    for (int j = 0; j < TOK_PER_BLK; j++) {
        const int t = ts[j];
        w[j] = (t >= N_PRE) ? W[(size_t)tid * INPUT_SIZE + (t - N_PRE)] : 0.f;
    }

    float4 v1 = make_float4(0.f, 0.f, 0.f, 0.f);
    if (t1 < N_PRE)
        v1 = reinterpret_cast<const float4*>(vectors + (size_t)t1 * VEC_DIM)[vq1];
    float4 v2 = make_float4(0.f, 0.f, 0.f, 0.f);
    if (has2 && t2 < N_PRE)
        v2 = reinterpret_cast<const float4*>(vectors + (size_t)t2 * VEC_DIM)[vq2];

    // ---- stores ----
#pragma unroll
    for (int j = 0; j < TOK_PER_BLK; j++)
        out[(size_t)(tok0 + j) * OUT_DIM + VEC_DIM + tid] = bias + w[j];

    // out row base = tok*2224 B -> 16B aligned, so float4 indexing is legal
    reinterpret_cast<float4*>(out + (size_t)vt1 * OUT_DIM)[vq1] = v1;
    if (has2)
        reinterpret_cast<float4*>(out + (size_t)vt2 * OUT_DIM)[vq2] = v2;
}

extern "C" void kernel_launch(void* const* d_in, const int* in_sizes, int n_in,
                              void* d_out, int out_size)
{
    const int*   batch   = (const int*)  d_in[0];
    const float* vectors = (const float*)d_in[1];
    const float* W       = (const float*)d_in[2];
    const float* b       = (const float*)d_in[3];
    float*       out     = (float*)d_out;

    encoder_fused<<<GRID, TPB>>>(batch, vectors, W, b, out);
}